// round 7
// baseline (speedup 1.0000x reference)
#include <cuda_runtime.h>
#include <cuda_bf16.h>
#include <cstdint>
#include <cstddef>

typedef unsigned long long ull;

#define BATCH 16
#define SLEN  2048
#define DIM   1024
#define HDIM  512
#define PDIM  3584

#define NCTA2 128          // phase-2 persistent CTAs (1/SM)

// ---------------- device scratch (bss; no runtime allocation) ----------------
__device__ float g_u   [(size_t)SLEN * BATCH * DIM];
__device__ float g_cand[(size_t)SLEN * BATCH * DIM];
__device__ float g_og  [(size_t)SLEN * BATCH * DIM];
__device__ float g_cosb[(size_t)SLEN * BATCH * HDIM];
__device__ float g_sinb[(size_t)SLEN * BATCH * HDIM];
__device__ float g_state[2][BATCH * DIM];
__device__ unsigned g_bar_count;   // returns to 0 after every barrier
__device__ unsigned g_bar_gen;     // monotonic across replays

// ---------------- helpers ----------------
__device__ __forceinline__ unsigned cvt_tf32(float f) {
    unsigned u;
    asm("cvt.rna.tf32.f32 %0, %1;" : "=r"(u) : "f"(f));
    return u;
}

__device__ __forceinline__ void mma_tf32(float* d, const unsigned* a, const unsigned* b) {
    asm volatile(
        "mma.sync.aligned.m16n8k8.row.col.f32.tf32.tf32.f32 "
        "{%0,%1,%2,%3}, {%4,%5,%6,%7}, {%8,%9}, {%0,%1,%2,%3};\n"
        : "+f"(d[0]), "+f"(d[1]), "+f"(d[2]), "+f"(d[3])
        : "r"(a[0]), "r"(a[1]), "r"(a[2]), "r"(a[3]),
          "r"(b[0]), "r"(b[1]));
}

__device__ __forceinline__ float sigmoidf_acc(float v) {
    return 1.0f / (1.0f + expf(-v));
}

// =====================================================================
// Phase 1: proj = x @ Wp^T + bp, fused nonlinearities, time-major gates
// grid (28, 256), 256 thr. CTA tile 128x128, K-chunk 32, cp.async 2-stage.
// (unchanged from R3 — known good at ~2.36 ms)
// =====================================================================
#define P1_STR 36   // smem row stride (floats): banks (4*grp+tig)%32 distinct

__device__ __forceinline__ void p1_issue(float* sA, float* sB,
                                         const float* __restrict__ x,
                                         const float* __restrict__ Wp,
                                         int m0, int n0, int k0, int tid) {
#pragma unroll
    for (int it = 0; it < 4; it++) {
        int f   = tid + 256 * it;
        int row = f >> 3;
        int c4  = f & 7;
        const float* gA = x  + (size_t)(m0 + row) * DIM + k0 + 4 * c4;
        const float* gB = Wp + (size_t)(n0 + row) * DIM + k0 + 4 * c4;
        unsigned sa = (unsigned)__cvta_generic_to_shared(sA + row * P1_STR + 4 * c4);
        unsigned sb = (unsigned)__cvta_generic_to_shared(sB + row * P1_STR + 4 * c4);
        asm volatile("cp.async.cg.shared.global [%0], [%1], 16;\n" :: "r"(sa), "l"(gA));
        asm volatile("cp.async.cg.shared.global [%0], [%1], 16;\n" :: "r"(sb), "l"(gB));
    }
}

__global__ void __launch_bounds__(256, 2)
phase1_kernel(const float* __restrict__ x,
              const float* __restrict__ Wp,
              const float* __restrict__ bp) {
    extern __shared__ float smem1[];
    float* sA[2] = { smem1,                 smem1 + 128 * P1_STR };
    float* sB[2] = { smem1 + 2*128*P1_STR,  smem1 + 3*128*P1_STR };

    const int tid  = threadIdx.x;
    const int m0   = blockIdx.y * 128;
    const int n0   = blockIdx.x * 128;
    const int warp = tid >> 5, lane = tid & 31;
    const int wm   = warp >> 2, wn = warp & 3;     // 2x4 warps, warp tile 64x32
    const int grp  = lane >> 2, tig = lane & 3;

    float acc[4][4][4];
#pragma unroll
    for (int a = 0; a < 4; a++)
#pragma unroll
        for (int b = 0; b < 4; b++)
#pragma unroll
            for (int c = 0; c < 4; c++) acc[a][b][c] = 0.0f;

    p1_issue(sA[0], sB[0], x, Wp, m0, n0, 0, tid);
    asm volatile("cp.async.commit_group;\n");

    for (int s = 0; s < 32; s++) {
        if (s < 31) {
            p1_issue(sA[(s + 1) & 1], sB[(s + 1) & 1], x, Wp, m0, n0, (s + 1) * 32, tid);
            asm volatile("cp.async.commit_group;\n");
            asm volatile("cp.async.wait_group 1;\n");
        } else {
            asm volatile("cp.async.wait_group 0;\n");
        }
        __syncthreads();

        const float* cA = sA[s & 1];
        const float* cB = sB[s & 1];
#pragma unroll
        for (int kc = 0; kc < 4; kc++) {
            const int kb = kc * 8;
            unsigned afr[4][4], bfr[4][2];
#pragma unroll
            for (int mf = 0; mf < 4; mf++) {
                const float* base = cA + (wm * 64 + mf * 16 + grp) * P1_STR + kb + tig;
                afr[mf][0] = cvt_tf32(base[0]);
                afr[mf][1] = cvt_tf32(base[8 * P1_STR]);
                afr[mf][2] = cvt_tf32(base[4]);
                afr[mf][3] = cvt_tf32(base[8 * P1_STR + 4]);
            }
#pragma unroll
            for (int nf = 0; nf < 4; nf++) {
                const float* base = cB + (wn * 32 + nf * 8 + grp) * P1_STR + kb + tig;
                bfr[nf][0] = cvt_tf32(base[0]);
                bfr[nf][1] = cvt_tf32(base[4]);
            }
#pragma unroll
            for (int mf = 0; mf < 4; mf++)
#pragma unroll
                for (int nf = 0; nf < 4; nf++)
                    mma_tf32(acc[mf][nf], afr[mf], bfr[nf]);
        }
        __syncthreads();
    }

    // epilogue: bias + nonlinearity, scatter time-major
#pragma unroll
    for (int mf = 0; mf < 4; mf++) {
#pragma unroll
        for (int r2 = 0; r2 < 2; r2++) {
            const int m    = m0 + wm * 64 + mf * 16 + grp + r2 * 8;
            const int t    = m & (SLEN - 1);
            const int bidx = m >> 11;
            const size_t ob1024 = ((size_t)t * BATCH + bidx) * (size_t)DIM;
            const size_t ob512  = ((size_t)t * BATCH + bidx) * (size_t)HDIM;
#pragma unroll
            for (int nf = 0; nf < 4; nf++) {
#pragma unroll
                for (int c = 0; c < 2; c++) {
                    const int n = n0 + wn * 32 + nf * 8 + 2 * tig + c;
                    const float v = acc[mf][nf][r2 * 2 + c] + bp[n];
                    if (n < DIM) {
                        g_u[ob1024 + n] = sigmoidf_acc(v);
                    } else if (n < DIM + HDIM) {
                        float sv, cv;
                        sincosf(v, &sv, &cv);
                        g_cosb[ob512 + (n - DIM)] = cv;
                        g_sinb[ob512 + (n - DIM)] = sv;
                    } else if (n < 2 * DIM + HDIM) {
                        g_cand[ob1024 + (n - (DIM + HDIM))] = tanhf(v);
                    } else {
                        g_og[ob1024 + (n - (2 * DIM + HDIM))] = sigmoidf_acc(v);
                    }
                }
            }
        }
    }
}

// =====================================================================
// Phase 2: persistent recurrence. 128 CTAs x 512 thr; CTA owns 8 j-rows.
// R4 changes: cp.async staging, register-halving shfl reduce, lean
// release/acquire barrier, pre-barrier gate prefetch.
// =====================================================================
__device__ __forceinline__ void grid_barrier() {
    __syncthreads();
    if (threadIdx.x == 0) {
        unsigned gen;
        asm volatile("ld.relaxed.gpu.global.u32 %0, [%1];"
                     : "=r"(gen) : "l"(&g_bar_gen) : "memory");
        unsigned old;
        asm volatile("atom.release.gpu.global.add.u32 %0, [%1], 1;"
                     : "=r"(old) : "l"(&g_bar_count) : "memory");
        if (old == NCTA2 - 1) {
            asm volatile("st.relaxed.gpu.global.u32 [%0], 0;"
                         :: "l"(&g_bar_count) : "memory");
            asm volatile("red.release.gpu.global.add.u32 [%0], 1;"
                         :: "l"(&g_bar_gen) : "memory");
        } else {
            unsigned cur;
            do {
                asm volatile("ld.acquire.gpu.global.u32 %0, [%1];"
                             : "=r"(cur) : "l"(&g_bar_gen) : "memory");
            } while (cur == gen);
        }
    }
    __syncthreads();
}

__global__ void __launch_bounds__(512, 1)
phase2_kernel(const float* __restrict__ Wt,
              const float* __restrict__ bt,
              float* __restrict__ out,
              int write_final) {
    extern __shared__ float smem2[];
    float* s_state = smem2;                  // [16][1024]
    float* s_red   = smem2 + BATCH * DIM;    // [8 groups][2 halves][16]

    const int tid  = threadIdx.x;
    const int lane = tid & 31;
    const int warp = tid >> 5;
    const int ks   = tid & 63;          // k-pair slice
    const int jh   = (tid >> 6) & 1;    // j half (4 rows each)
    const int bg   = tid >> 7;          // batch group (4 b each)
    const int cta  = blockIdx.x;

    // persistent Wt registers: w2[jj][i] packs Wt[j][2*(ks+64i)], Wt[j][2*(ks+64i)+1]
    ull w2[4][8];
#pragma unroll
    for (int jj = 0; jj < 4; jj++) {
        const int j = 8 * cta + 4 * jh + jj;
#pragma unroll
        for (int i = 0; i < 8; i++)
            w2[jj][i] = *(const ull*)(Wt + (size_t)j * DIM + 2 * (ks + 64 * i));
    }

    // epilogue-thread constants (valid for tid<128)
    const int b_e   = tid >> 3;
    const int jl_e  = tid & 7;
    const int jglob = 8 * cta + jl_e;
    const int hp    = jglob >> 1;
    const int bbE = b_e & 3, bgE = b_e >> 2, jjE = jl_e & 3, jhE = jl_e >> 2;
    const int gE  = jhE + 2 * bgE;
    const int iE  = jjE * 4 + bbE;
    const int iP  = (jjE ^ 1) * 4 + bbE;

    // gates for step t (prefetched one barrier ahead)
    float gu = 0.f, gcd = 0.f, gog = 0.f, gc = 0.f, gs = 0.f;
    if (tid < 128) {
        const size_t ob = (size_t)0 * BATCH + b_e;
        gu  = g_u   [ob * DIM  + jglob];
        gcd = g_cand[ob * DIM  + jglob];
        gog = g_og  [ob * DIM  + jglob];
        gc  = g_cosb[ob * HDIM + hp];
        gs  = g_sinb[ob * HDIM + hp];
    }

    for (int t = 0; t < SLEN; t++) {
        float ps_me = 0.f, ps_pa = 0.f;
        if (t == 0) {
            if (tid < 128) { ps_me = bt[jglob]; ps_pa = bt[jglob ^ 1]; }
        } else {
            // ---- stage state (L2 -> smem) via cp.async (bypasses L1 + regs) ----
            const float* src = g_state[t & 1];
#pragma unroll
            for (int q = 0; q < 8; q++) {
                const int f4 = tid + 512 * q;
                unsigned sp = (unsigned)__cvta_generic_to_shared(s_state + 4 * f4);
                asm volatile("cp.async.cg.shared.global [%0], [%1], 16;\n"
                             :: "r"(sp), "l"(src + 4 * f4));
            }
            asm volatile("cp.async.commit_group;\n");
            asm volatile("cp.async.wait_group 0;\n");
            __syncthreads();

            // ---- matvec partials: acc[jj][bb] packed f32x2 over k parity ----
            ull acc[4][4];
#pragma unroll
            for (int jj = 0; jj < 4; jj++)
#pragma unroll
                for (int bb = 0; bb < 4; bb++) acc[jj][bb] = 0ull;

#pragma unroll
            for (int bb = 0; bb < 4; bb++) {
                const float* sp = s_state + (4 * bg + bb) * DIM + 2 * ks;
                ull s2[8];
#pragma unroll
                for (int i = 0; i < 8; i++) s2[i] = *(const ull*)(sp + 128 * i);
#pragma unroll
                for (int jj = 0; jj < 4; jj++)
#pragma unroll
                    for (int i = 0; i < 8; i++)
                        asm("fma.rn.f32x2 %0, %1, %2, %0;"
                            : "+l"(acc[jj][bb]) : "l"(w2[jj][i]), "l"(s2[i]));
            }

            // ---- collapse pairs, register-halving butterfly over 32 lanes ----
            // v[idx], idx = jj*4+bb. Levels 16/8/4/2 halve the live set
            // (kept-index bit = lane bit), final level 1 is a plain add.
            // Lane L ends holding output f = (L>>1)&15, duplicated on L^1.
            float v[16];
#pragma unroll
            for (int jj = 0; jj < 4; jj++)
#pragma unroll
                for (int bb = 0; bb < 4; bb++) {
                    float2 f = *(float2*)&acc[jj][bb];
                    v[jj * 4 + bb] = f.x + f.y;
                }
            {
                const bool lo16 = (lane & 16) == 0;
#pragma unroll
                for (int j = 0; j < 8; j++) {
                    float send = lo16 ? v[j + 8] : v[j];
                    float recv = __shfl_xor_sync(0xffffffffu, send, 16);
                    v[j] = (lo16 ? v[j] : v[j + 8]) + recv;
                }
                const bool lo8 = (lane & 8) == 0;
#pragma unroll
                for (int j = 0; j < 4; j++) {
                    float send = lo8 ? v[j + 4] : v[j];
                    float recv = __shfl_xor_sync(0xffffffffu, send, 8);
                    v[j] = (lo8 ? v[j] : v[j + 4]) + recv;
                }
                const bool lo4 = (lane & 4) == 0;
#pragma unroll
                for (int j = 0; j < 2; j++) {
                    float send = lo4 ? v[j + 2] : v[j];
                    float recv = __shfl_xor_sync(0xffffffffu, send, 4);
                    v[j] = (lo4 ? v[j] : v[j + 2]) + recv;
                }
                const bool lo2 = (lane & 2) == 0;
                {
                    float send = lo2 ? v[1] : v[0];
                    float recv = __shfl_xor_sync(0xffffffffu, send, 2);
                    v[0] = (lo2 ? v[0] : v[1]) + recv;
                }
                v[0] += __shfl_xor_sync(0xffffffffu, v[0], 1);
            }
            if ((lane & 1) == 0)
                s_red[(warp >> 1) * 32 + (warp & 1) * 16 + ((lane >> 1) & 15)] = v[0];
            __syncthreads();

            if (tid < 128) {
                ps_me = s_red[gE * 32 + iE] + s_red[gE * 32 + 16 + iE] + bt[jglob];
                ps_pa = s_red[gE * 32 + iP] + s_red[gE * 32 + 16 + iP] + bt[jglob ^ 1];
            }
        }

        // ---- rotation + gates + writes (uses gates for step t) ----
        if (tid < 128) {
            float ts;
            if (jl_e & 1) ts = ps_pa * gs + ps_me * gc;   // r1 = p0*sin + p1*cos
            else          ts = ps_me * gc - ps_pa * gs;   // r0 = p0*cos - p1*sin
            const float ns = gu * ts + (1.0f - gu) * gcd;
            out[(size_t)b_e * SLEN * DIM + (size_t)t * DIM + jglob] = gog * ns;
            __stcg(&g_state[(t + 1) & 1][b_e * DIM + jglob], ns);
            if (write_final && t == SLEN - 1)
                out[(size_t)BATCH * SLEN * DIM + (size_t)b_e * DIM + jglob] = ns;
        }

        if (t < SLEN - 1) {
            // prefetch gates for t+1: DRAM latency overlaps the barrier spin
            if (tid < 128) {
                const size_t ob = (size_t)(t + 1) * BATCH + b_e;
                gu  = g_u   [ob * DIM  + jglob];
                gcd = g_cand[ob * DIM  + jglob];
                gog = g_og  [ob * DIM  + jglob];
                gc  = g_cosb[ob * HDIM + hp];
                gs  = g_sinb[ob * HDIM + hp];
            }
            grid_barrier();
        }
    }
}

// =====================================================================
extern "C" void kernel_launch(void* const* d_in, const int* in_sizes, int n_in,
                              void* d_out, int out_size) {
    const float* x  = (const float*)d_in[0];
    const float* Wp = (const float*)d_in[1];
    const float* bp = (const float*)d_in[2];
    const float* Wt = (const float*)d_in[3];
    const float* bt = (const float*)d_in[4];
    float* out = (float*)d_out;

    const int smem1 = 4 * 128 * P1_STR * (int)sizeof(float);           // 73728
    const int smem2 = (BATCH * DIM + 8 * 2 * 16) * (int)sizeof(float); // 66560
    cudaFuncSetAttribute(phase1_kernel, cudaFuncAttributeMaxDynamicSharedMemorySize, smem1);
    cudaFuncSetAttribute(phase2_kernel, cudaFuncAttributeMaxDynamicSharedMemorySize, smem2);

    const long long need = (long long)BATCH * SLEN * DIM + (long long)BATCH * DIM;
    const int write_final = ((long long)out_size >= need) ? 1 : 0;

    dim3 g1(PDIM / 128, (BATCH * SLEN) / 128);   // (28, 256)
    phase1_kernel<<<g1, 256, smem1>>>(x, Wp, bp);
    phase2_kernel<<<NCTA2, 512, smem2>>>(Wt, bt, out, write_final);
}

// round 8
// speedup vs baseline: 1.0348x; 1.0348x over previous
#include <cuda_runtime.h>
#include <cuda_bf16.h>
#include <cstdint>
#include <cstddef>

typedef unsigned long long ull;

#define BATCH 16
#define SLEN  2048
#define DIM   1024
#define HDIM  512
#define PDIM  3584

#define NCTA2 128          // phase-2 persistent CTAs (1/SM), 4 quarters of 32

// ---------------- device scratch (bss; no runtime allocation) ----------------
__device__ float g_u   [(size_t)SLEN * BATCH * DIM];
__device__ float g_cand[(size_t)SLEN * BATCH * DIM];
__device__ float g_og  [(size_t)SLEN * BATCH * DIM];
__device__ float g_cosb[(size_t)SLEN * BATCH * HDIM];
__device__ float g_sinb[(size_t)SLEN * BATCH * HDIM];
__device__ float g_state[2][BATCH * DIM];
__device__ unsigned g_qcnt[4];     // quarter progress counters; reset to 0 at kernel end
__device__ unsigned g_bar_count;   // end-of-kernel classic barrier (self-restoring)
__device__ unsigned g_bar_gen;     // monotonic across replays

// ---------------- helpers ----------------
__device__ __forceinline__ unsigned cvt_tf32(float f) {
    unsigned u;
    asm("cvt.rna.tf32.f32 %0, %1;" : "=r"(u) : "f"(f));
    return u;
}

__device__ __forceinline__ void mma_tf32(float* d, const unsigned* a, const unsigned* b) {
    asm volatile(
        "mma.sync.aligned.m16n8k8.row.col.f32.tf32.tf32.f32 "
        "{%0,%1,%2,%3}, {%4,%5,%6,%7}, {%8,%9}, {%0,%1,%2,%3};\n"
        : "+f"(d[0]), "+f"(d[1]), "+f"(d[2]), "+f"(d[3])
        : "r"(a[0]), "r"(a[1]), "r"(a[2]), "r"(a[3]),
          "r"(b[0]), "r"(b[1]));
}

__device__ __forceinline__ float sigmoidf_acc(float v) {
    return 1.0f / (1.0f + expf(-v));
}

// =====================================================================
// Phase 1: proj = x @ Wp^T + bp, fused nonlinearities, time-major gates
// grid (28, 256), 256 thr. CTA tile 128x128, K-chunk 32, cp.async 2-stage.
// (unchanged — known good at ~2.36 ms)
// =====================================================================
#define P1_STR 36   // smem row stride (floats): banks (4*grp+tig)%32 distinct

__device__ __forceinline__ void p1_issue(float* sA, float* sB,
                                         const float* __restrict__ x,
                                         const float* __restrict__ Wp,
                                         int m0, int n0, int k0, int tid) {
#pragma unroll
    for (int it = 0; it < 4; it++) {
        int f   = tid + 256 * it;
        int row = f >> 3;
        int c4  = f & 7;
        const float* gA = x  + (size_t)(m0 + row) * DIM + k0 + 4 * c4;
        const float* gB = Wp + (size_t)(n0 + row) * DIM + k0 + 4 * c4;
        unsigned sa = (unsigned)__cvta_generic_to_shared(sA + row * P1_STR + 4 * c4);
        unsigned sb = (unsigned)__cvta_generic_to_shared(sB + row * P1_STR + 4 * c4);
        asm volatile("cp.async.cg.shared.global [%0], [%1], 16;\n" :: "r"(sa), "l"(gA));
        asm volatile("cp.async.cg.shared.global [%0], [%1], 16;\n" :: "r"(sb), "l"(gB));
    }
}

__global__ void __launch_bounds__(256, 2)
phase1_kernel(const float* __restrict__ x,
              const float* __restrict__ Wp,
              const float* __restrict__ bp) {
    extern __shared__ float smem1[];
    float* sA[2] = { smem1,                 smem1 + 128 * P1_STR };
    float* sB[2] = { smem1 + 2*128*P1_STR,  smem1 + 3*128*P1_STR };

    const int tid  = threadIdx.x;
    const int m0   = blockIdx.y * 128;
    const int n0   = blockIdx.x * 128;
    const int warp = tid >> 5, lane = tid & 31;
    const int wm   = warp >> 2, wn = warp & 3;     // 2x4 warps, warp tile 64x32
    const int grp  = lane >> 2, tig = lane & 3;

    float acc[4][4][4];
#pragma unroll
    for (int a = 0; a < 4; a++)
#pragma unroll
        for (int b = 0; b < 4; b++)
#pragma unroll
            for (int c = 0; c < 4; c++) acc[a][b][c] = 0.0f;

    p1_issue(sA[0], sB[0], x, Wp, m0, n0, 0, tid);
    asm volatile("cp.async.commit_group;\n");

    for (int s = 0; s < 32; s++) {
        if (s < 31) {
            p1_issue(sA[(s + 1) & 1], sB[(s + 1) & 1], x, Wp, m0, n0, (s + 1) * 32, tid);
            asm volatile("cp.async.commit_group;\n");
            asm volatile("cp.async.wait_group 1;\n");
        } else {
            asm volatile("cp.async.wait_group 0;\n");
        }
        __syncthreads();

        const float* cA = sA[s & 1];
        const float* cB = sB[s & 1];
#pragma unroll
        for (int kc = 0; kc < 4; kc++) {
            const int kb = kc * 8;
            unsigned afr[4][4], bfr[4][2];
#pragma unroll
            for (int mf = 0; mf < 4; mf++) {
                const float* base = cA + (wm * 64 + mf * 16 + grp) * P1_STR + kb + tig;
                afr[mf][0] = cvt_tf32(base[0]);
                afr[mf][1] = cvt_tf32(base[8 * P1_STR]);
                afr[mf][2] = cvt_tf32(base[4]);
                afr[mf][3] = cvt_tf32(base[8 * P1_STR + 4]);
            }
#pragma unroll
            for (int nf = 0; nf < 4; nf++) {
                const float* base = cB + (wn * 32 + nf * 8 + grp) * P1_STR + kb + tig;
                bfr[nf][0] = cvt_tf32(base[0]);
                bfr[nf][1] = cvt_tf32(base[4]);
            }
#pragma unroll
            for (int mf = 0; mf < 4; mf++)
#pragma unroll
                for (int nf = 0; nf < 4; nf++)
                    mma_tf32(acc[mf][nf], afr[mf], bfr[nf]);
        }
        __syncthreads();
    }

    // epilogue: bias + nonlinearity, scatter time-major
#pragma unroll
    for (int mf = 0; mf < 4; mf++) {
#pragma unroll
        for (int r2 = 0; r2 < 2; r2++) {
            const int m    = m0 + wm * 64 + mf * 16 + grp + r2 * 8;
            const int t    = m & (SLEN - 1);
            const int bidx = m >> 11;
            const size_t ob1024 = ((size_t)t * BATCH + bidx) * (size_t)DIM;
            const size_t ob512  = ((size_t)t * BATCH + bidx) * (size_t)HDIM;
#pragma unroll
            for (int nf = 0; nf < 4; nf++) {
#pragma unroll
                for (int c = 0; c < 2; c++) {
                    const int n = n0 + wn * 32 + nf * 8 + 2 * tig + c;
                    const float v = acc[mf][nf][r2 * 2 + c] + bp[n];
                    if (n < DIM) {
                        g_u[ob1024 + n] = sigmoidf_acc(v);
                    } else if (n < DIM + HDIM) {
                        float sv, cv;
                        sincosf(v, &sv, &cv);
                        g_cosb[ob512 + (n - DIM)] = cv;
                        g_sinb[ob512 + (n - DIM)] = sv;
                    } else if (n < 2 * DIM + HDIM) {
                        g_cand[ob1024 + (n - (DIM + HDIM))] = tanhf(v);
                    } else {
                        g_og[ob1024 + (n - (2 * DIM + HDIM))] = sigmoidf_acc(v);
                    }
                }
            }
        }
    }
}

// =====================================================================
// Phase 2: persistent recurrence with quarter-grained flag pipeline.
// 128 CTAs x 512 thr; CTA owns 8 j-rows. Quarter q (CTAs 32q..32q+31)
// produces state k-range [256q, 256q+256). Consumers wait per-quarter,
// stage 16KB per quarter, interleave cp.async wait_group with FMA.
// =====================================================================
__device__ __forceinline__ void spin_ge(const unsigned* p, unsigned target) {
    unsigned cur;
    do {
        asm volatile("ld.acquire.gpu.global.u32 %0, [%1];"
                     : "=r"(cur) : "l"(p) : "memory");
    } while (cur < target);
}

__device__ __forceinline__ void end_barrier() {
    __syncthreads();
    if (threadIdx.x == 0) {
        unsigned gen;
        asm volatile("ld.relaxed.gpu.global.u32 %0, [%1];"
                     : "=r"(gen) : "l"(&g_bar_gen) : "memory");
        unsigned old;
        asm volatile("atom.release.gpu.global.add.u32 %0, [%1], 1;"
                     : "=r"(old) : "l"(&g_bar_count) : "memory");
        if (old == NCTA2 - 1) {
            asm volatile("st.relaxed.gpu.global.u32 [%0], 0;"
                         :: "l"(&g_bar_count) : "memory");
            asm volatile("red.release.gpu.global.add.u32 [%0], 1;"
                         :: "l"(&g_bar_gen) : "memory");
        } else {
            unsigned cur;
            do {
                asm volatile("ld.acquire.gpu.global.u32 %0, [%1];"
                             : "=r"(cur) : "l"(&g_bar_gen) : "memory");
            } while (cur == gen);
        }
    }
    __syncthreads();
}

__global__ void __launch_bounds__(512, 1)
phase2_kernel(const float* __restrict__ Wt,
              const float* __restrict__ bt,
              float* __restrict__ out,
              int write_final) {
    extern __shared__ float smem2[];
    float* s_state = smem2;                  // [16][1024], mirrors global layout
    float* s_red   = smem2 + BATCH * DIM;    // [8 groups][2 halves][16]

    const int tid  = threadIdx.x;
    const int lane = tid & 31;
    const int warp = tid >> 5;
    const int ks   = tid & 63;          // k-pair slice
    const int jh   = (tid >> 6) & 1;    // j half (4 rows each)
    const int bg   = tid >> 7;          // batch group (4 b each)
    const int cta  = blockIdx.x;
    const int myq  = cta >> 5;          // my producer quarter

    // persistent Wt registers: w2[jj][i] packs Wt[j][2*(ks+64i)], Wt[j][2*(ks+64i)+1]
    ull w2[4][8];
#pragma unroll
    for (int jj = 0; jj < 4; jj++) {
        const int j = 8 * cta + 4 * jh + jj;
#pragma unroll
        for (int i = 0; i < 8; i++)
            w2[jj][i] = *(const ull*)(Wt + (size_t)j * DIM + 2 * (ks + 64 * i));
    }

    // epilogue-thread constants (valid for tid<128)
    const int b_e   = tid >> 3;
    const int jl_e  = tid & 7;
    const int jglob = 8 * cta + jl_e;
    const int hp    = jglob >> 1;
    const int bbE = b_e & 3, bgE = b_e >> 2, jjE = jl_e & 3, jhE = jl_e >> 2;
    const int gE  = jhE + 2 * bgE;
    const int iE  = jjE * 4 + bbE;
    const int iP  = (jjE ^ 1) * 4 + bbE;

    // staging addressing (per quarter): f4 = b*256 + q*64 + (tid&31) + 32w, b = tid>>5
    const int st_b   = tid >> 5;
    const int st_idx = tid & 31;
    const unsigned s_state_sh = (unsigned)__cvta_generic_to_shared(s_state);

    // gates for step t (prefetched one step ahead)
    float gu = 0.f, gcd = 0.f, gog = 0.f, gc = 0.f, gs = 0.f;
    if (tid < 128) {
        gu  = g_u   [(size_t)b_e * DIM  + jglob];
        gcd = g_cand[(size_t)b_e * DIM  + jglob];
        gog = g_og  [(size_t)b_e * DIM  + jglob];
        gc  = g_cosb[(size_t)b_e * HDIM + hp];
        gs  = g_sinb[(size_t)b_e * HDIM + hp];
    }

    for (int t = 0; t < SLEN; t++) {
        float ps_me = 0.f, ps_pa = 0.f;
        if (t == 0) {
            if (tid < 128) { ps_me = bt[jglob]; ps_pa = bt[jglob ^ 1]; }
        } else {
            const float* src = g_state[t & 1];
            const unsigned tgt = 32u * (unsigned)t;

            // ---- stage: spin per quarter, issue 16KB, one commit group each ----
#pragma unroll
            for (int q = 0; q < 4; q++) {
                if (tid == 0) spin_ge(&g_qcnt[q], tgt);
                __syncthreads();
                const int f4 = st_b * 256 + q * 64 + st_idx;
                asm volatile("cp.async.cg.shared.global [%0], [%1], 16;\n"
                             :: "r"(s_state_sh + 16u * (unsigned)f4), "l"(src + 4 * f4));
                asm volatile("cp.async.cg.shared.global [%0], [%1], 16;\n"
                             :: "r"(s_state_sh + 16u * (unsigned)(f4 + 32)), "l"(src + 4 * (f4 + 32)));
                asm volatile("cp.async.commit_group;\n");
            }

            // ---- FMA, quarter-pipelined against staging flight ----
            ull acc[4][4];
#pragma unroll
            for (int jj = 0; jj < 4; jj++)
#pragma unroll
                for (int bb = 0; bb < 4; bb++) acc[jj][bb] = 0ull;

#define P2_FMA_QUARTER(Q)                                                          \
            do {                                                                   \
                __syncthreads();                                                   \
                _Pragma("unroll")                                                  \
                for (int bb = 0; bb < 4; bb++) {                                   \
                    const float* sp = s_state + (4 * bg + bb) * DIM + 2 * ks + 256 * (Q); \
                    ull s2a = *(const ull*)(sp);                                   \
                    ull s2b = *(const ull*)(sp + 128);                             \
                    _Pragma("unroll")                                              \
                    for (int jj = 0; jj < 4; jj++) {                               \
                        asm("fma.rn.f32x2 %0, %1, %2, %0;"                         \
                            : "+l"(acc[jj][bb]) : "l"(w2[jj][2 * (Q)]), "l"(s2a)); \
                        asm("fma.rn.f32x2 %0, %1, %2, %0;"                         \
                            : "+l"(acc[jj][bb]) : "l"(w2[jj][2 * (Q) + 1]), "l"(s2b)); \
                    }                                                              \
                }                                                                  \
            } while (0)

            asm volatile("cp.async.wait_group 3;\n");
            P2_FMA_QUARTER(0);
            asm volatile("cp.async.wait_group 2;\n");
            P2_FMA_QUARTER(1);
            asm volatile("cp.async.wait_group 1;\n");
            P2_FMA_QUARTER(2);
            asm volatile("cp.async.wait_group 0;\n");
            P2_FMA_QUARTER(3);

            // ---- collapse pairs, register-halving butterfly over 32 lanes ----
            float v[16];
#pragma unroll
            for (int jj = 0; jj < 4; jj++)
#pragma unroll
                for (int bb = 0; bb < 4; bb++) {
                    float2 f = *(float2*)&acc[jj][bb];
                    v[jj * 4 + bb] = f.x + f.y;
                }
            {
                const bool lo16 = (lane & 16) == 0;
#pragma unroll
                for (int j = 0; j < 8; j++) {
                    float send = lo16 ? v[j + 8] : v[j];
                    float recv = __shfl_xor_sync(0xffffffffu, send, 16);
                    v[j] = (lo16 ? v[j] : v[j + 8]) + recv;
                }
                const bool lo8 = (lane & 8) == 0;
#pragma unroll
                for (int j = 0; j < 4; j++) {
                    float send = lo8 ? v[j + 4] : v[j];
                    float recv = __shfl_xor_sync(0xffffffffu, send, 8);
                    v[j] = (lo8 ? v[j] : v[j + 4]) + recv;
                }
                const bool lo4 = (lane & 4) == 0;
#pragma unroll
                for (int j = 0; j < 2; j++) {
                    float send = lo4 ? v[j + 2] : v[j];
                    float recv = __shfl_xor_sync(0xffffffffu, send, 4);
                    v[j] = (lo4 ? v[j] : v[j + 2]) + recv;
                }
                const bool lo2 = (lane & 2) == 0;
                {
                    float send = lo2 ? v[1] : v[0];
                    float recv = __shfl_xor_sync(0xffffffffu, send, 2);
                    v[0] = (lo2 ? v[0] : v[1]) + recv;
                }
                v[0] += __shfl_xor_sync(0xffffffffu, v[0], 1);
            }
            if ((lane & 1) == 0)
                s_red[(warp >> 1) * 32 + (warp & 1) * 16 + ((lane >> 1) & 15)] = v[0];
            __syncthreads();

            if (tid < 128) {
                ps_me = s_red[gE * 32 + iE] + s_red[gE * 32 + 16 + iE] + bt[jglob];
                ps_pa = s_red[gE * 32 + iP] + s_red[gE * 32 + 16 + iP] + bt[jglob ^ 1];
            }
        }

        // ---- rotation + gates + writes (uses gates for step t) ----
        if (tid < 128) {
            float ts;
            if (jl_e & 1) ts = ps_pa * gs + ps_me * gc;   // r1 = p0*sin + p1*cos
            else          ts = ps_me * gc - ps_pa * gs;   // r0 = p0*cos - p1*sin
            const float ns = gu * ts + (1.0f - gu) * gcd;
            out[(size_t)b_e * SLEN * DIM + (size_t)t * DIM + jglob] = gog * ns;
            __stcg(&g_state[(t + 1) & 1][b_e * DIM + jglob], ns);
            if (write_final && t == SLEN - 1)
                out[(size_t)BATCH * SLEN * DIM + (size_t)b_e * DIM + jglob] = ns;
        }

        if (t < SLEN - 1) {
            // prefetch gates for t+1 (DRAM latency overlaps next spin+staging)
            if (tid < 128) {
                const size_t ob = (size_t)(t + 1) * BATCH + b_e;
                gu  = g_u   [ob * DIM  + jglob];
                gcd = g_cand[ob * DIM  + jglob];
                gog = g_og  [ob * DIM  + jglob];
                gc  = g_cosb[ob * HDIM + hp];
                gs  = g_sinb[ob * HDIM + hp];
            }
            // publish: state t+1 written by this CTA -> bump my quarter counter
            __syncthreads();
            if (tid == 0)
                asm volatile("red.release.gpu.global.add.u32 [%0], 1;"
                             :: "l"(&g_qcnt[myq]) : "memory");
        }
    }

    // ---- end of run: classic barrier, then CTA0 resets quarter counters ----
    end_barrier();
    if (cta == 0 && tid == 0) {
#pragma unroll
        for (int q = 0; q < 4; q++)
            asm volatile("st.relaxed.gpu.global.u32 [%0], 0;"
                         :: "l"(&g_qcnt[q]) : "memory");
    }
}

// =====================================================================
extern "C" void kernel_launch(void* const* d_in, const int* in_sizes, int n_in,
                              void* d_out, int out_size) {
    const float* x  = (const float*)d_in[0];
    const float* Wp = (const float*)d_in[1];
    const float* bp = (const float*)d_in[2];
    const float* Wt = (const float*)d_in[3];
    const float* bt = (const float*)d_in[4];
    float* out = (float*)d_out;

    const int smem1 = 4 * 128 * P1_STR * (int)sizeof(float);           // 73728
    const int smem2 = (BATCH * DIM + 8 * 2 * 16) * (int)sizeof(float); // 66560
    cudaFuncSetAttribute(phase1_kernel, cudaFuncAttributeMaxDynamicSharedMemorySize, smem1);
    cudaFuncSetAttribute(phase2_kernel, cudaFuncAttributeMaxDynamicSharedMemorySize, smem2);

    const long long need = (long long)BATCH * SLEN * DIM + (long long)BATCH * DIM;
    const int write_final = ((long long)out_size >= need) ? 1 : 0;

    dim3 g1(PDIM / 128, (BATCH * SLEN) / 128);   // (28, 256)
    phase1_kernel<<<g1, 256, smem1>>>(x, Wp, bp);
    phase2_kernel<<<NCTA2, 512, smem2>>>(Wt, bt, out, write_final);
}

// round 9
// speedup vs baseline: 1.1788x; 1.1392x over previous
#include <cuda_runtime.h>
#include <cuda_bf16.h>
#include <cstdint>
#include <cstddef>

typedef unsigned long long ull;

#define BATCH 16
#define SLEN  2048
#define DIM   1024
#define HDIM  512
#define PDIM  3584

#define NCTA2 128          // phase-2 persistent CTAs (1/SM), 4 quarters of 32

// ---------------- device scratch (bss; no runtime allocation) ----------------
__device__ float g_u   [(size_t)SLEN * BATCH * DIM];
__device__ float g_cand[(size_t)SLEN * BATCH * DIM];
__device__ float g_og  [(size_t)SLEN * BATCH * DIM];
__device__ float g_cosb[(size_t)SLEN * BATCH * HDIM];
__device__ float g_sinb[(size_t)SLEN * BATCH * HDIM];
__device__ float g_state[2][BATCH * DIM];
__device__ unsigned g_qcnt[4];     // quarter progress counters; reset to 0 at kernel end
__device__ unsigned g_bar_count;   // end-of-kernel classic barrier (self-restoring)
__device__ unsigned g_bar_gen;     // monotonic across replays

// ---------------- helpers ----------------
__device__ __forceinline__ unsigned cvt_tf32(float f) {
    unsigned u;
    asm("cvt.rna.tf32.f32 %0, %1;" : "=r"(u) : "f"(f));
    return u;
}

__device__ __forceinline__ void mma_tf32(float* d, const unsigned* a, const unsigned* b) {
    asm volatile(
        "mma.sync.aligned.m16n8k8.row.col.f32.tf32.tf32.f32 "
        "{%0,%1,%2,%3}, {%4,%5,%6,%7}, {%8,%9}, {%0,%1,%2,%3};\n"
        : "+f"(d[0]), "+f"(d[1]), "+f"(d[2]), "+f"(d[3])
        : "r"(a[0]), "r"(a[1]), "r"(a[2]), "r"(a[3]),
          "r"(b[0]), "r"(b[1]));
}

__device__ __forceinline__ float sigmoidf_acc(float v) {
    return 1.0f / (1.0f + expf(-v));
}

// =====================================================================
// Phase 1: proj = x @ Wp^T + bp, fused nonlinearities, time-major gates
// grid (28, 256), 256 thr. CTA tile 128x128, K-chunk 32, cp.async 2-stage.
// (unchanged — HMMA-throughput bound at ~2.34 ms; tcgen05 is the next lever)
// =====================================================================
#define P1_STR 36   // smem row stride (floats): banks (4*grp+tig)%32 distinct

__device__ __forceinline__ void p1_issue(float* sA, float* sB,
                                         const float* __restrict__ x,
                                         const float* __restrict__ Wp,
                                         int m0, int n0, int k0, int tid) {
#pragma unroll
    for (int it = 0; it < 4; it++) {
        int f   = tid + 256 * it;
        int row = f >> 3;
        int c4  = f & 7;
        const float* gA = x  + (size_t)(m0 + row) * DIM + k0 + 4 * c4;
        const float* gB = Wp + (size_t)(n0 + row) * DIM + k0 + 4 * c4;
        unsigned sa = (unsigned)__cvta_generic_to_shared(sA + row * P1_STR + 4 * c4);
        unsigned sb = (unsigned)__cvta_generic_to_shared(sB + row * P1_STR + 4 * c4);
        asm volatile("cp.async.cg.shared.global [%0], [%1], 16;\n" :: "r"(sa), "l"(gA));
        asm volatile("cp.async.cg.shared.global [%0], [%1], 16;\n" :: "r"(sb), "l"(gB));
    }
}

__global__ void __launch_bounds__(256, 2)
phase1_kernel(const float* __restrict__ x,
              const float* __restrict__ Wp,
              const float* __restrict__ bp) {
    extern __shared__ float smem1[];
    float* sA[2] = { smem1,                 smem1 + 128 * P1_STR };
    float* sB[2] = { smem1 + 2*128*P1_STR,  smem1 + 3*128*P1_STR };

    const int tid  = threadIdx.x;
    const int m0   = blockIdx.y * 128;
    const int n0   = blockIdx.x * 128;
    const int warp = tid >> 5, lane = tid & 31;
    const int wm   = warp >> 2, wn = warp & 3;     // 2x4 warps, warp tile 64x32
    const int grp  = lane >> 2, tig = lane & 3;

    float acc[4][4][4];
#pragma unroll
    for (int a = 0; a < 4; a++)
#pragma unroll
        for (int b = 0; b < 4; b++)
#pragma unroll
            for (int c = 0; c < 4; c++) acc[a][b][c] = 0.0f;

    p1_issue(sA[0], sB[0], x, Wp, m0, n0, 0, tid);
    asm volatile("cp.async.commit_group;\n");

    for (int s = 0; s < 32; s++) {
        if (s < 31) {
            p1_issue(sA[(s + 1) & 1], sB[(s + 1) & 1], x, Wp, m0, n0, (s + 1) * 32, tid);
            asm volatile("cp.async.commit_group;\n");
            asm volatile("cp.async.wait_group 1;\n");
        } else {
            asm volatile("cp.async.wait_group 0;\n");
        }
        __syncthreads();

        const float* cA = sA[s & 1];
        const float* cB = sB[s & 1];
#pragma unroll
        for (int kc = 0; kc < 4; kc++) {
            const int kb = kc * 8;
            unsigned afr[4][4], bfr[4][2];
#pragma unroll
            for (int mf = 0; mf < 4; mf++) {
                const float* base = cA + (wm * 64 + mf * 16 + grp) * P1_STR + kb + tig;
                afr[mf][0] = cvt_tf32(base[0]);
                afr[mf][1] = cvt_tf32(base[8 * P1_STR]);
                afr[mf][2] = cvt_tf32(base[4]);
                afr[mf][3] = cvt_tf32(base[8 * P1_STR + 4]);
            }
#pragma unroll
            for (int nf = 0; nf < 4; nf++) {
                const float* base = cB + (wn * 32 + nf * 8 + grp) * P1_STR + kb + tig;
                bfr[nf][0] = cvt_tf32(base[0]);
                bfr[nf][1] = cvt_tf32(base[4]);
            }
#pragma unroll
            for (int mf = 0; mf < 4; mf++)
#pragma unroll
                for (int nf = 0; nf < 4; nf++)
                    mma_tf32(acc[mf][nf], afr[mf], bfr[nf]);
        }
        __syncthreads();
    }

    // epilogue: bias + nonlinearity, scatter time-major
#pragma unroll
    for (int mf = 0; mf < 4; mf++) {
#pragma unroll
        for (int r2 = 0; r2 < 2; r2++) {
            const int m    = m0 + wm * 64 + mf * 16 + grp + r2 * 8;
            const int t    = m & (SLEN - 1);
            const int bidx = m >> 11;
            const size_t ob1024 = ((size_t)t * BATCH + bidx) * (size_t)DIM;
            const size_t ob512  = ((size_t)t * BATCH + bidx) * (size_t)HDIM;
#pragma unroll
            for (int nf = 0; nf < 4; nf++) {
#pragma unroll
                for (int c = 0; c < 2; c++) {
                    const int n = n0 + wn * 32 + nf * 8 + 2 * tig + c;
                    const float v = acc[mf][nf][r2 * 2 + c] + bp[n];
                    if (n < DIM) {
                        g_u[ob1024 + n] = sigmoidf_acc(v);
                    } else if (n < DIM + HDIM) {
                        float sv, cv;
                        sincosf(v, &sv, &cv);
                        g_cosb[ob512 + (n - DIM)] = cv;
                        g_sinb[ob512 + (n - DIM)] = sv;
                    } else if (n < 2 * DIM + HDIM) {
                        g_cand[ob1024 + (n - (DIM + HDIM))] = tanhf(v);
                    } else {
                        g_og[ob1024 + (n - (2 * DIM + HDIM))] = sigmoidf_acc(v);
                    }
                }
            }
        }
    }
}

// =====================================================================
// Phase 2: persistent recurrence, quarter flags with PARALLEL detection.
// 128 CTAs x 512 thr; CTA owns 8 j-rows. Quarter q (CTAs 32q..32q+31)
// produces state k-range [256q, 256q+256). One parallel spin (lanes 0-3
// of warp 0, MLP=4), one sync, then all staging issued; FMA overlaps
// later-quarter flight via 4 commit groups.
// =====================================================================
__device__ __forceinline__ void end_barrier() {
    __syncthreads();
    if (threadIdx.x == 0) {
        unsigned gen;
        asm volatile("ld.relaxed.gpu.global.u32 %0, [%1];"
                     : "=r"(gen) : "l"(&g_bar_gen) : "memory");
        unsigned old;
        asm volatile("atom.release.gpu.global.add.u32 %0, [%1], 1;"
                     : "=r"(old) : "l"(&g_bar_count) : "memory");
        if (old == NCTA2 - 1) {
            asm volatile("st.relaxed.gpu.global.u32 [%0], 0;"
                         :: "l"(&g_bar_count) : "memory");
            asm volatile("red.release.gpu.global.add.u32 [%0], 1;"
                         :: "l"(&g_bar_gen) : "memory");
        } else {
            unsigned cur;
            do {
                asm volatile("ld.acquire.gpu.global.u32 %0, [%1];"
                             : "=r"(cur) : "l"(&g_bar_gen) : "memory");
            } while (cur == gen);
        }
    }
    __syncthreads();
}

__global__ void __launch_bounds__(512, 1)
phase2_kernel(const float* __restrict__ Wt,
              const float* __restrict__ bt,
              float* __restrict__ out,
              int write_final) {
    extern __shared__ float smem2[];
    float* s_state = smem2;                  // [16][1024], mirrors global layout
    float* s_red   = smem2 + BATCH * DIM;    // [8 groups][2 halves][16]

    const int tid  = threadIdx.x;
    const int lane = tid & 31;
    const int warp = tid >> 5;
    const int ks   = tid & 63;          // k-pair slice
    const int jh   = (tid >> 6) & 1;    // j half (4 rows each)
    const int bg   = tid >> 7;          // batch group (4 b each)
    const int cta  = blockIdx.x;
    const int myq  = cta >> 5;          // my producer quarter

    // persistent Wt registers: w2[jj][i] packs Wt[j][2*(ks+64i)], Wt[j][2*(ks+64i)+1]
    ull w2[4][8];
#pragma unroll
    for (int jj = 0; jj < 4; jj++) {
        const int j = 8 * cta + 4 * jh + jj;
#pragma unroll
        for (int i = 0; i < 8; i++)
            w2[jj][i] = *(const ull*)(Wt + (size_t)j * DIM + 2 * (ks + 64 * i));
    }

    // epilogue-thread constants (valid for tid<128)
    const int b_e   = tid >> 3;
    const int jl_e  = tid & 7;
    const int jglob = 8 * cta + jl_e;
    const int hp    = jglob >> 1;
    const int bbE = b_e & 3, bgE = b_e >> 2, jjE = jl_e & 3, jhE = jl_e >> 2;
    const int gE  = jhE + 2 * bgE;
    const int iE  = jjE * 4 + bbE;
    const int iP  = (jjE ^ 1) * 4 + bbE;

    // staging addressing (per quarter): f4 = b*256 + q*64 + (tid&31) + 32w, b = tid>>5
    const int st_b   = tid >> 5;
    const int st_idx = tid & 31;
    const unsigned s_state_sh = (unsigned)__cvta_generic_to_shared(s_state);

    // gates for step t (prefetched one step ahead)
    float gu = 0.f, gcd = 0.f, gog = 0.f, gc = 0.f, gs = 0.f;
    if (tid < 128) {
        gu  = g_u   [(size_t)b_e * DIM  + jglob];
        gcd = g_cand[(size_t)b_e * DIM  + jglob];
        gog = g_og  [(size_t)b_e * DIM  + jglob];
        gc  = g_cosb[(size_t)b_e * HDIM + hp];
        gs  = g_sinb[(size_t)b_e * HDIM + hp];
    }

    for (int t = 0; t < SLEN; t++) {
        float ps_me = 0.f, ps_pa = 0.f;
        if (t == 0) {
            if (tid < 128) { ps_me = bt[jglob]; ps_pa = bt[jglob ^ 1]; }
        } else {
            const float* src = g_state[t & 1];
            const unsigned tgt = 32u * (unsigned)t;

            // ---- parallel detect: lanes 0-3 of warp 0 spin on the 4 counters ----
            if (warp == 0 && lane < 4) {
                unsigned cur;
                do {
                    asm volatile("ld.acquire.gpu.global.u32 %0, [%1];"
                                 : "=r"(cur) : "l"(&g_qcnt[lane]) : "memory");
                } while (cur < tgt);
            }
            __syncthreads();

            // ---- issue all staging (16KB per quarter, 4 commit groups) ----
#pragma unroll
            for (int q = 0; q < 4; q++) {
                const int f4 = st_b * 256 + q * 64 + st_idx;
                asm volatile("cp.async.cg.shared.global [%0], [%1], 16;\n"
                             :: "r"(s_state_sh + 16u * (unsigned)f4), "l"(src + 4 * f4));
                asm volatile("cp.async.cg.shared.global [%0], [%1], 16;\n"
                             :: "r"(s_state_sh + 16u * (unsigned)(f4 + 32)), "l"(src + 4 * (f4 + 32)));
                asm volatile("cp.async.commit_group;\n");
            }

            // ---- FMA, quarter-pipelined against staging flight ----
            ull acc[4][4];
#pragma unroll
            for (int jj = 0; jj < 4; jj++)
#pragma unroll
                for (int bb = 0; bb < 4; bb++) acc[jj][bb] = 0ull;

#define P2_FMA_QUARTER(Q)                                                          \
            do {                                                                   \
                __syncthreads();                                                   \
                _Pragma("unroll")                                                  \
                for (int bb = 0; bb < 4; bb++) {                                   \
                    const float* sp = s_state + (4 * bg + bb) * DIM + 2 * ks + 256 * (Q); \
                    ull s2a = *(const ull*)(sp);                                   \
                    ull s2b = *(const ull*)(sp + 128);                             \
                    _Pragma("unroll")                                              \
                    for (int jj = 0; jj < 4; jj++) {                               \
                        asm("fma.rn.f32x2 %0, %1, %2, %0;"                         \
                            : "+l"(acc[jj][bb]) : "l"(w2[jj][2 * (Q)]), "l"(s2a)); \
                        asm("fma.rn.f32x2 %0, %1, %2, %0;"                         \
                            : "+l"(acc[jj][bb]) : "l"(w2[jj][2 * (Q) + 1]), "l"(s2b)); \
                    }                                                              \
                }                                                                  \
            } while (0)

            asm volatile("cp.async.wait_group 3;\n");
            P2_FMA_QUARTER(0);
            asm volatile("cp.async.wait_group 2;\n");
            P2_FMA_QUARTER(1);
            asm volatile("cp.async.wait_group 1;\n");
            P2_FMA_QUARTER(2);
            asm volatile("cp.async.wait_group 0;\n");
            P2_FMA_QUARTER(3);

            // ---- collapse pairs, register-halving butterfly over 32 lanes ----
            float v[16];
#pragma unroll
            for (int jj = 0; jj < 4; jj++)
#pragma unroll
                for (int bb = 0; bb < 4; bb++) {
                    float2 f = *(float2*)&acc[jj][bb];
                    v[jj * 4 + bb] = f.x + f.y;
                }
            {
                const bool lo16 = (lane & 16) == 0;
#pragma unroll
                for (int j = 0; j < 8; j++) {
                    float send = lo16 ? v[j + 8] : v[j];
                    float recv = __shfl_xor_sync(0xffffffffu, send, 16);
                    v[j] = (lo16 ? v[j] : v[j + 8]) + recv;
                }
                const bool lo8 = (lane & 8) == 0;
#pragma unroll
                for (int j = 0; j < 4; j++) {
                    float send = lo8 ? v[j + 4] : v[j];
                    float recv = __shfl_xor_sync(0xffffffffu, send, 8);
                    v[j] = (lo8 ? v[j] : v[j + 4]) + recv;
                }
                const bool lo4 = (lane & 4) == 0;
#pragma unroll
                for (int j = 0; j < 2; j++) {
                    float send = lo4 ? v[j + 2] : v[j];
                    float recv = __shfl_xor_sync(0xffffffffu, send, 4);
                    v[j] = (lo4 ? v[j] : v[j + 2]) + recv;
                }
                const bool lo2 = (lane & 2) == 0;
                {
                    float send = lo2 ? v[1] : v[0];
                    float recv = __shfl_xor_sync(0xffffffffu, send, 2);
                    v[0] = (lo2 ? v[0] : v[1]) + recv;
                }
                v[0] += __shfl_xor_sync(0xffffffffu, v[0], 1);
            }
            if ((lane & 1) == 0)
                s_red[(warp >> 1) * 32 + (warp & 1) * 16 + ((lane >> 1) & 15)] = v[0];
            __syncthreads();

            if (tid < 128) {
                ps_me = s_red[gE * 32 + iE] + s_red[gE * 32 + 16 + iE] + bt[jglob];
                ps_pa = s_red[gE * 32 + iP] + s_red[gE * 32 + 16 + iP] + bt[jglob ^ 1];
            }
        }

        // ---- rotation + gates + writes (uses gates for step t) ----
        if (tid < 128) {
            float ts;
            if (jl_e & 1) ts = ps_pa * gs + ps_me * gc;   // r1 = p0*sin + p1*cos
            else          ts = ps_me * gc - ps_pa * gs;   // r0 = p0*cos - p1*sin
            const float ns = gu * ts + (1.0f - gu) * gcd;
            out[(size_t)b_e * SLEN * DIM + (size_t)t * DIM + jglob] = gog * ns;
            __stcg(&g_state[(t + 1) & 1][b_e * DIM + jglob], ns);
            if (write_final && t == SLEN - 1)
                out[(size_t)BATCH * SLEN * DIM + (size_t)b_e * DIM + jglob] = ns;
        }

        if (t < SLEN - 1) {
            // prefetch gates for t+1 (DRAM latency overlaps next detect+staging)
            if (tid < 128) {
                const size_t ob = (size_t)(t + 1) * BATCH + b_e;
                gu  = g_u   [ob * DIM  + jglob];
                gcd = g_cand[ob * DIM  + jglob];
                gog = g_og  [ob * DIM  + jglob];
                gc  = g_cosb[ob * HDIM + hp];
                gs  = g_sinb[ob * HDIM + hp];
            }
            // publish: state t+1 written by this CTA -> bump my quarter counter
            __syncthreads();
            if (tid == 0)
                asm volatile("red.release.gpu.global.add.u32 [%0], 1;"
                             :: "l"(&g_qcnt[myq]) : "memory");
        }
    }

    // ---- end of run: classic barrier, then CTA0 resets quarter counters ----
    end_barrier();
    if (cta == 0 && tid == 0) {
#pragma unroll
        for (int q = 0; q < 4; q++)
            asm volatile("st.relaxed.gpu.global.u32 [%0], 0;"
                         :: "l"(&g_qcnt[q]) : "memory");
    }
}

// =====================================================================
extern "C" void kernel_launch(void* const* d_in, const int* in_sizes, int n_in,
                              void* d_out, int out_size) {
    const float* x  = (const float*)d_in[0];
    const float* Wp = (const float*)d_in[1];
    const float* bp = (const float*)d_in[2];
    const float* Wt = (const float*)d_in[3];
    const float* bt = (const float*)d_in[4];
    float* out = (float*)d_out;

    const int smem1 = 4 * 128 * P1_STR * (int)sizeof(float);           // 73728
    const int smem2 = (BATCH * DIM + 8 * 2 * 16) * (int)sizeof(float); // 66560
    cudaFuncSetAttribute(phase1_kernel, cudaFuncAttributeMaxDynamicSharedMemorySize, smem1);
    cudaFuncSetAttribute(phase2_kernel, cudaFuncAttributeMaxDynamicSharedMemorySize, smem2);

    const long long need = (long long)BATCH * SLEN * DIM + (long long)BATCH * DIM;
    const int write_final = ((long long)out_size >= need) ? 1 : 0;

    dim3 g1(PDIM / 128, (BATCH * SLEN) / 128);   // (28, 256)
    phase1_kernel<<<g1, 256, smem1>>>(x, Wp, bp);
    phase2_kernel<<<NCTA2, 512, smem2>>>(Wt, bt, out, write_final);
}

// round 10
// speedup vs baseline: 1.2253x; 1.0395x over previous
#include <cuda_runtime.h>
#include <cuda_bf16.h>
#include <cstdint>
#include <cstddef>

typedef unsigned long long ull;

#define BATCH 16
#define SLEN  2048
#define DIM   1024
#define HDIM  512
#define PDIM  3584

#define NCTA2 128   // phase-2 CTAs: 32 j-blocks x 4 b-columns

// ---------------- device scratch (bss; no runtime allocation) ----------------
__device__ float g_u   [(size_t)SLEN * BATCH * DIM];
__device__ float g_cand[(size_t)SLEN * BATCH * DIM];
__device__ float g_og  [(size_t)SLEN * BATCH * DIM];
__device__ float g_cosb[(size_t)SLEN * BATCH * HDIM];
__device__ float g_sinb[(size_t)SLEN * BATCH * HDIM];
__device__ float g_state[2][BATCH * DIM];
__device__ unsigned g_cnt16[16];   // [bcol][qj] progress counters; reset at kernel end
__device__ unsigned g_bar_count;   // end-of-kernel classic barrier (self-restoring)
__device__ unsigned g_bar_gen;     // monotonic across replays

// ---------------- helpers ----------------
__device__ __forceinline__ unsigned cvt_tf32(float f) {
    unsigned u;
    asm("cvt.rna.tf32.f32 %0, %1;" : "=r"(u) : "f"(f));
    return u;
}

__device__ __forceinline__ void mma_tf32(float* d, const unsigned* a, const unsigned* b) {
    asm volatile(
        "mma.sync.aligned.m16n8k8.row.col.f32.tf32.tf32.f32 "
        "{%0,%1,%2,%3}, {%4,%5,%6,%7}, {%8,%9}, {%0,%1,%2,%3};\n"
        : "+f"(d[0]), "+f"(d[1]), "+f"(d[2]), "+f"(d[3])
        : "r"(a[0]), "r"(a[1]), "r"(a[2]), "r"(a[3]),
          "r"(b[0]), "r"(b[1]));
}

__device__ __forceinline__ float sigmoidf_acc(float v) {
    return 1.0f / (1.0f + expf(-v));
}

// =====================================================================
// Phase 1: proj = x @ Wp^T + bp, fused nonlinearities, time-major gates
// (unchanged — HMMA-throughput bound at ~2.34 ms; next target after p2)
// =====================================================================
#define P1_STR 36   // smem row stride (floats): banks (4*grp+tig)%32 distinct

__device__ __forceinline__ void p1_issue(float* sA, float* sB,
                                         const float* __restrict__ x,
                                         const float* __restrict__ Wp,
                                         int m0, int n0, int k0, int tid) {
#pragma unroll
    for (int it = 0; it < 4; it++) {
        int f   = tid + 256 * it;
        int row = f >> 3;
        int c4  = f & 7;
        const float* gA = x  + (size_t)(m0 + row) * DIM + k0 + 4 * c4;
        const float* gB = Wp + (size_t)(n0 + row) * DIM + k0 + 4 * c4;
        unsigned sa = (unsigned)__cvta_generic_to_shared(sA + row * P1_STR + 4 * c4);
        unsigned sb = (unsigned)__cvta_generic_to_shared(sB + row * P1_STR + 4 * c4);
        asm volatile("cp.async.cg.shared.global [%0], [%1], 16;\n" :: "r"(sa), "l"(gA));
        asm volatile("cp.async.cg.shared.global [%0], [%1], 16;\n" :: "r"(sb), "l"(gB));
    }
}

__global__ void __launch_bounds__(256, 2)
phase1_kernel(const float* __restrict__ x,
              const float* __restrict__ Wp,
              const float* __restrict__ bp) {
    extern __shared__ float smem1[];
    float* sA[2] = { smem1,                 smem1 + 128 * P1_STR };
    float* sB[2] = { smem1 + 2*128*P1_STR,  smem1 + 3*128*P1_STR };

    const int tid  = threadIdx.x;
    const int m0   = blockIdx.y * 128;
    const int n0   = blockIdx.x * 128;
    const int warp = tid >> 5, lane = tid & 31;
    const int wm   = warp >> 2, wn = warp & 3;
    const int grp  = lane >> 2, tig = lane & 3;

    float acc[4][4][4];
#pragma unroll
    for (int a = 0; a < 4; a++)
#pragma unroll
        for (int b = 0; b < 4; b++)
#pragma unroll
            for (int c = 0; c < 4; c++) acc[a][b][c] = 0.0f;

    p1_issue(sA[0], sB[0], x, Wp, m0, n0, 0, tid);
    asm volatile("cp.async.commit_group;\n");

    for (int s = 0; s < 32; s++) {
        if (s < 31) {
            p1_issue(sA[(s + 1) & 1], sB[(s + 1) & 1], x, Wp, m0, n0, (s + 1) * 32, tid);
            asm volatile("cp.async.commit_group;\n");
            asm volatile("cp.async.wait_group 1;\n");
        } else {
            asm volatile("cp.async.wait_group 0;\n");
        }
        __syncthreads();

        const float* cA = sA[s & 1];
        const float* cB = sB[s & 1];
#pragma unroll
        for (int kc = 0; kc < 4; kc++) {
            const int kb = kc * 8;
            unsigned afr[4][4], bfr[4][2];
#pragma unroll
            for (int mf = 0; mf < 4; mf++) {
                const float* base = cA + (wm * 64 + mf * 16 + grp) * P1_STR + kb + tig;
                afr[mf][0] = cvt_tf32(base[0]);
                afr[mf][1] = cvt_tf32(base[8 * P1_STR]);
                afr[mf][2] = cvt_tf32(base[4]);
                afr[mf][3] = cvt_tf32(base[8 * P1_STR + 4]);
            }
#pragma unroll
            for (int nf = 0; nf < 4; nf++) {
                const float* base = cB + (wn * 32 + nf * 8 + grp) * P1_STR + kb + tig;
                bfr[nf][0] = cvt_tf32(base[0]);
                bfr[nf][1] = cvt_tf32(base[4]);
            }
#pragma unroll
            for (int mf = 0; mf < 4; mf++)
#pragma unroll
                for (int nf = 0; nf < 4; nf++)
                    mma_tf32(acc[mf][nf], afr[mf], bfr[nf]);
        }
        __syncthreads();
    }

#pragma unroll
    for (int mf = 0; mf < 4; mf++) {
#pragma unroll
        for (int r2 = 0; r2 < 2; r2++) {
            const int m    = m0 + wm * 64 + mf * 16 + grp + r2 * 8;
            const int t    = m & (SLEN - 1);
            const int bidx = m >> 11;
            const size_t ob1024 = ((size_t)t * BATCH + bidx) * (size_t)DIM;
            const size_t ob512  = ((size_t)t * BATCH + bidx) * (size_t)HDIM;
#pragma unroll
            for (int nf = 0; nf < 4; nf++) {
#pragma unroll
                for (int c = 0; c < 2; c++) {
                    const int n = n0 + wn * 32 + nf * 8 + 2 * tig + c;
                    const float v = acc[mf][nf][r2 * 2 + c] + bp[n];
                    if (n < DIM) {
                        g_u[ob1024 + n] = sigmoidf_acc(v);
                    } else if (n < DIM + HDIM) {
                        float sv, cv;
                        sincosf(v, &sv, &cv);
                        g_cosb[ob512 + (n - DIM)] = cv;
                        g_sinb[ob512 + (n - DIM)] = sv;
                    } else if (n < 2 * DIM + HDIM) {
                        g_cand[ob1024 + (n - (DIM + HDIM))] = tanhf(v);
                    } else {
                        g_og[ob1024 + (n - (2 * DIM + HDIM))] = sigmoidf_acc(v);
                    }
                }
            }
        }
    }
}

// =====================================================================
// Phase 2: persistent recurrence, batch-split columns.
// CTA c = (jb = c>>2, bcol = c&3): owns j in [32jb,32jb+32), b in
// [4bcol,4bcol+4). 4 independent 32-CTA columns; 16 flag counters
// [bcol][qj] with 8 producers each (target 8t). Stages only 16KB/step.
// =====================================================================
__device__ __forceinline__ void end_barrier() {
    __syncthreads();
    if (threadIdx.x == 0) {
        unsigned gen;
        asm volatile("ld.relaxed.gpu.global.u32 %0, [%1];"
                     : "=r"(gen) : "l"(&g_bar_gen) : "memory");
        unsigned old;
        asm volatile("atom.release.gpu.global.add.u32 %0, [%1], 1;"
                     : "=r"(old) : "l"(&g_bar_count) : "memory");
        if (old == NCTA2 - 1) {
            asm volatile("st.relaxed.gpu.global.u32 [%0], 0;"
                         :: "l"(&g_bar_count) : "memory");
            asm volatile("red.release.gpu.global.add.u32 [%0], 1;"
                         :: "l"(&g_bar_gen) : "memory");
        } else {
            unsigned cur;
            do {
                asm volatile("ld.acquire.gpu.global.u32 %0, [%1];"
                             : "=r"(cur) : "l"(&g_bar_gen) : "memory");
            } while (cur == gen);
        }
    }
    __syncthreads();
}

__global__ void __launch_bounds__(512, 1)
phase2_kernel(const float* __restrict__ Wt,
              const float* __restrict__ bt,
              float* __restrict__ out,
              int write_final) {
    extern __shared__ float smem2[];
    float* s_state = smem2;                   // [4 b][1024 k]
    float* s_red   = smem2 + 4 * DIM;         // [8 jg][2 halves][16]

    const int tid  = threadIdx.x;
    const int lane = tid & 31;
    const int warp = tid >> 5;
    const int ks   = tid & 63;          // k-pair slice (covers k = 2(ks+64i))
    const int jg   = tid >> 6;          // j group: 8 groups of 4 j
    const int cta  = blockIdx.x;
    const int bcol = cta & 3;           // batch column (4 batches)
    const int jb   = cta >> 2;          // j block (32 j-rows)
    const int myflag = bcol * 4 + (jb >> 3);   // my quarter counter

    // persistent Wt registers: w2[jj][i] packs Wt[j][2*(ks+64i)] pair,
    // j = 32*jb + 4*jg + jj
    ull w2[4][8];
#pragma unroll
    for (int jj = 0; jj < 4; jj++) {
        const int j = 32 * jb + 4 * jg + jj;
#pragma unroll
        for (int i = 0; i < 8; i++)
            w2[jj][i] = *(const ull*)(Wt + (size_t)j * DIM + 2 * (ks + 64 * i));
    }

    // epilogue-thread constants (valid for tid<128): 32 j x 4 b outputs
    const int bl_e  = tid >> 5;          // local batch 0..3
    const int jl_e  = tid & 31;          // local j 0..31
    const int b_e   = 4 * bcol + bl_e;
    const int jglob = 32 * jb + jl_e;
    const int hp    = jglob >> 1;
    const int jgE   = jl_e >> 2, jjE = jl_e & 3;
    const int iE    = jjE * 4 + bl_e;
    const int iP    = (jjE ^ 1) * 4 + bl_e;

    // staging constants: per quarter 256 float4 (4 b x 64), threads 0..255
    const int st_bl  = tid >> 6;         // 0..3 for tid<256
    const int st_idx = tid & 63;
    const unsigned s_state_sh = (unsigned)__cvta_generic_to_shared(s_state);

    // gates for step t (prefetched one step ahead)
    float gu = 0.f, gcd = 0.f, gog = 0.f, gc = 0.f, gs = 0.f;
    if (tid < 128) {
        gu  = g_u   [(size_t)b_e * DIM  + jglob];
        gcd = g_cand[(size_t)b_e * DIM  + jglob];
        gog = g_og  [(size_t)b_e * DIM  + jglob];
        gc  = g_cosb[(size_t)b_e * HDIM + hp];
        gs  = g_sinb[(size_t)b_e * HDIM + hp];
    }

    for (int t = 0; t < SLEN; t++) {
        float ps_me = 0.f, ps_pa = 0.f;
        if (t == 0) {
            if (tid < 128) { ps_me = bt[jglob]; ps_pa = bt[jglob ^ 1]; }
        } else {
            const float4* src4 = (const float4*)g_state[t & 1];
            const unsigned tgt = 8u * (unsigned)t;

            // ---- parallel detect: lanes 0-3 spin on my column's 4 quarters ----
            if (warp == 0 && lane < 4) {
                unsigned cur;
                do {
                    asm volatile("ld.acquire.gpu.global.u32 %0, [%1];"
                                 : "=r"(cur) : "l"(&g_cnt16[bcol * 4 + lane]) : "memory");
                } while (cur < tgt);
            }
            __syncthreads();

            // ---- stage my 4 batches (4KB per quarter, 4 commit groups) ----
#pragma unroll
            for (int q = 0; q < 4; q++) {
                if (tid < 256) {
                    const int sidx = st_bl * 256 + q * 64 + st_idx;       // smem f4 idx
                    const int gidx = (4 * bcol + st_bl) * 256 + q * 64 + st_idx;
                    asm volatile("cp.async.cg.shared.global [%0], [%1], 16;\n"
                                 :: "r"(s_state_sh + 16u * (unsigned)sidx),
                                    "l"(src4 + gidx));
                }
                asm volatile("cp.async.commit_group;\n");
            }

            // ---- FMA, quarter-pipelined against staging flight ----
            ull acc[4][4];
#pragma unroll
            for (int jj = 0; jj < 4; jj++)
#pragma unroll
                for (int bl = 0; bl < 4; bl++) acc[jj][bl] = 0ull;

#define P2_FMA_QUARTER(Q)                                                          \
            do {                                                                   \
                __syncthreads();                                                   \
                _Pragma("unroll")                                                  \
                for (int bl = 0; bl < 4; bl++) {                                   \
                    const float* sp = s_state + bl * DIM + 2 * ks + 256 * (Q);     \
                    ull s2a = *(const ull*)(sp);                                   \
                    ull s2b = *(const ull*)(sp + 128);                             \
                    _Pragma("unroll")                                              \
                    for (int jj = 0; jj < 4; jj++) {                               \
                        asm("fma.rn.f32x2 %0, %1, %2, %0;"                         \
                            : "+l"(acc[jj][bl]) : "l"(w2[jj][2 * (Q)]), "l"(s2a)); \
                        asm("fma.rn.f32x2 %0, %1, %2, %0;"                         \
                            : "+l"(acc[jj][bl]) : "l"(w2[jj][2 * (Q) + 1]), "l"(s2b)); \
                    }                                                              \
                }                                                                  \
            } while (0)

            asm volatile("cp.async.wait_group 3;\n");
            P2_FMA_QUARTER(0);
            asm volatile("cp.async.wait_group 2;\n");
            P2_FMA_QUARTER(1);
            asm volatile("cp.async.wait_group 1;\n");
            P2_FMA_QUARTER(2);
            asm volatile("cp.async.wait_group 0;\n");
            P2_FMA_QUARTER(3);

            // ---- collapse pairs, register-halving butterfly over 32 lanes ----
            // v[jj*4+bl]; warp = jg*2 + ks-half; halves combined via s_red.
            float v[16];
#pragma unroll
            for (int jj = 0; jj < 4; jj++)
#pragma unroll
                for (int bl = 0; bl < 4; bl++) {
                    float2 f = *(float2*)&acc[jj][bl];
                    v[jj * 4 + bl] = f.x + f.y;
                }
            {
                const bool lo16 = (lane & 16) == 0;
#pragma unroll
                for (int j = 0; j < 8; j++) {
                    float send = lo16 ? v[j + 8] : v[j];
                    float recv = __shfl_xor_sync(0xffffffffu, send, 16);
                    v[j] = (lo16 ? v[j] : v[j + 8]) + recv;
                }
                const bool lo8 = (lane & 8) == 0;
#pragma unroll
                for (int j = 0; j < 4; j++) {
                    float send = lo8 ? v[j + 4] : v[j];
                    float recv = __shfl_xor_sync(0xffffffffu, send, 8);
                    v[j] = (lo8 ? v[j] : v[j + 4]) + recv;
                }
                const bool lo4 = (lane & 4) == 0;
#pragma unroll
                for (int j = 0; j < 2; j++) {
                    float send = lo4 ? v[j + 2] : v[j];
                    float recv = __shfl_xor_sync(0xffffffffu, send, 4);
                    v[j] = (lo4 ? v[j] : v[j + 2]) + recv;
                }
                const bool lo2 = (lane & 2) == 0;
                {
                    float send = lo2 ? v[1] : v[0];
                    float recv = __shfl_xor_sync(0xffffffffu, send, 2);
                    v[0] = (lo2 ? v[0] : v[1]) + recv;
                }
                v[0] += __shfl_xor_sync(0xffffffffu, v[0], 1);
            }
            if ((lane & 1) == 0)
                s_red[(warp >> 1) * 32 + (warp & 1) * 16 + ((lane >> 1) & 15)] = v[0];
            __syncthreads();

            if (tid < 128) {
                ps_me = s_red[jgE * 32 + iE] + s_red[jgE * 32 + 16 + iE] + bt[jglob];
                ps_pa = s_red[jgE * 32 + iP] + s_red[jgE * 32 + 16 + iP] + bt[jglob ^ 1];
            }
        }

        // ---- rotation + gates + writes (uses gates for step t) ----
        if (tid < 128) {
            float ts;
            if (jl_e & 1) ts = ps_pa * gs + ps_me * gc;   // r1 = p0*sin + p1*cos
            else          ts = ps_me * gc - ps_pa * gs;   // r0 = p0*cos - p1*sin
            const float ns = gu * ts + (1.0f - gu) * gcd;
            out[(size_t)b_e * SLEN * DIM + (size_t)t * DIM + jglob] = gog * ns;
            __stcg(&g_state[(t + 1) & 1][b_e * DIM + jglob], ns);
            if (write_final && t == SLEN - 1)
                out[(size_t)BATCH * SLEN * DIM + (size_t)b_e * DIM + jglob] = ns;
        }

        if (t < SLEN - 1) {
            // prefetch gates for t+1 (DRAM latency overlaps next detect+staging)
            if (tid < 128) {
                const size_t ob = (size_t)(t + 1) * BATCH + b_e;
                gu  = g_u   [ob * DIM  + jglob];
                gcd = g_cand[ob * DIM  + jglob];
                gog = g_og  [ob * DIM  + jglob];
                gc  = g_cosb[ob * HDIM + hp];
                gs  = g_sinb[ob * HDIM + hp];
            }
            // publish: my 32-j slice of state t+1 is written
            __syncthreads();
            if (tid == 0)
                asm volatile("red.release.gpu.global.add.u32 [%0], 1;"
                             :: "l"(&g_cnt16[myflag]) : "memory");
        }
    }

    // ---- end of run: classic barrier, then CTA0 resets counters ----
    end_barrier();
    if (cta == 0 && tid == 0) {
#pragma unroll
        for (int q = 0; q < 16; q++)
            asm volatile("st.relaxed.gpu.global.u32 [%0], 0;"
                         :: "l"(&g_cnt16[q]) : "memory");
    }
}

// =====================================================================
extern "C" void kernel_launch(void* const* d_in, const int* in_sizes, int n_in,
                              void* d_out, int out_size) {
    const float* x  = (const float*)d_in[0];
    const float* Wp = (const float*)d_in[1];
    const float* bp = (const float*)d_in[2];
    const float* Wt = (const float*)d_in[3];
    const float* bt = (const float*)d_in[4];
    float* out = (float*)d_out;

    const int smem1 = 4 * 128 * P1_STR * (int)sizeof(float);            // 73728
    const int smem2 = (4 * DIM + 8 * 2 * 16) * (int)sizeof(float);      // 17408
    cudaFuncSetAttribute(phase1_kernel, cudaFuncAttributeMaxDynamicSharedMemorySize, smem1);
    cudaFuncSetAttribute(phase2_kernel, cudaFuncAttributeMaxDynamicSharedMemorySize, smem2);

    const long long need = (long long)BATCH * SLEN * DIM + (long long)BATCH * DIM;
    const int write_final = ((long long)out_size >= need) ? 1 : 0;

    dim3 g1(PDIM / 128, (BATCH * SLEN) / 128);   // (28, 256)
    phase1_kernel<<<g1, 256, smem1>>>(x, Wp, bp);
    phase2_kernel<<<NCTA2, 512, smem2>>>(Wt, bt, out, write_final);
}

// round 13
// speedup vs baseline: 1.3005x; 1.0613x over previous
#include <cuda_runtime.h>
#include <cuda_bf16.h>
#include <cstdint>
#include <cstddef>

typedef unsigned long long ull;

#define BATCH 16
#define SLEN  2048
#define DIM   1024
#define HDIM  512
#define PDIM  3584

#define NCTA2 128   // phase-2 CTAs: 32 j-blocks x 4 b-columns

// ---------------- device scratch (bss; no runtime allocation) ----------------
__device__ float g_u   [(size_t)SLEN * BATCH * DIM];
__device__ float g_cand[(size_t)SLEN * BATCH * DIM];
__device__ float g_og  [(size_t)SLEN * BATCH * DIM];
__device__ float g_cosb[(size_t)SLEN * BATCH * HDIM];
__device__ float g_sinb[(size_t)SLEN * BATCH * HDIM];
__device__ float g_state[2][BATCH * DIM];
__device__ unsigned g_cnt16[16];   // [bcol][qj] progress counters; reset at kernel end
__device__ unsigned g_bar_count;   // end-of-kernel classic barrier (self-restoring)
__device__ unsigned g_bar_gen;     // monotonic across replays

// tf32-pre-rounded operand copies (phase1 inner loop loads these raw)
__device__ float g_xcvt [(size_t)BATCH * SLEN * DIM];   // 128 MB
__device__ float g_wpcvt[(size_t)PDIM * DIM];           // 14 MB

// ---------------- helpers ----------------
__device__ __forceinline__ unsigned cvt_tf32(float f) {
    unsigned u;
    asm("cvt.rna.tf32.f32 %0, %1;" : "=r"(u) : "f"(f));
    return u;
}

__device__ __forceinline__ void mma_tf32(float* d, const unsigned* a, const unsigned* b) {
    asm volatile(
        "mma.sync.aligned.m16n8k8.row.col.f32.tf32.tf32.f32 "
        "{%0,%1,%2,%3}, {%4,%5,%6,%7}, {%8,%9}, {%0,%1,%2,%3};\n"
        : "+f"(d[0]), "+f"(d[1]), "+f"(d[2]), "+f"(d[3])
        : "r"(a[0]), "r"(a[1]), "r"(a[2]), "r"(a[3]),
          "r"(b[0]), "r"(b[1]));
}

__device__ __forceinline__ float sigmoidf_acc(float v) {
    return 1.0f / (1.0f + expf(-v));
}

// =====================================================================
// tf32 pre-rounding bulk copy (runs once per launch, ~60us)
// =====================================================================
__global__ void cvt_kernel(const float* __restrict__ src, float* __restrict__ dst, int n4) {
    const float4* s4 = (const float4*)src;
    float4* d4 = (float4*)dst;
    for (int i = blockIdx.x * blockDim.x + threadIdx.x; i < n4; i += gridDim.x * blockDim.x) {
        float4 v = s4[i];
        v.x = __uint_as_float(cvt_tf32(v.x));
        v.y = __uint_as_float(cvt_tf32(v.y));
        v.z = __uint_as_float(cvt_tf32(v.z));
        v.w = __uint_as_float(cvt_tf32(v.w));
        d4[i] = v;
    }
}

// =====================================================================
// Phase 1: proj = xr @ Wpr^T + bp on PRE-ROUNDED operands; fused
// nonlinearities; time-major gate scatter. grid (28, 256), 256 thr.
// CTA tile 128x128, K-chunk 32, cp.async 2-stage. No per-fragment CVT:
// mma.sync tf32 drops low mantissa bits = identity on pre-rounded data.
// =====================================================================
#define P1_STR 36   // smem row stride (floats): banks (4*grp+tig)%32 distinct

__device__ __forceinline__ void p1_issue(float* sA, float* sB,
                                         const float* __restrict__ x,
                                         const float* __restrict__ Wp,
                                         int m0, int n0, int k0, int tid) {
#pragma unroll
    for (int it = 0; it < 4; it++) {
        int f   = tid + 256 * it;
        int row = f >> 3;
        int c4  = f & 7;
        const float* gA = x  + (size_t)(m0 + row) * DIM + k0 + 4 * c4;
        const float* gB = Wp + (size_t)(n0 + row) * DIM + k0 + 4 * c4;
        unsigned sa = (unsigned)__cvta_generic_to_shared(sA + row * P1_STR + 4 * c4);
        unsigned sb = (unsigned)__cvta_generic_to_shared(sB + row * P1_STR + 4 * c4);
        asm volatile("cp.async.cg.shared.global [%0], [%1], 16;\n" :: "r"(sa), "l"(gA));
        asm volatile("cp.async.cg.shared.global [%0], [%1], 16;\n" :: "r"(sb), "l"(gB));
    }
}

__global__ void __launch_bounds__(256, 2)
phase1_kernel(const float* __restrict__ bp) {
    extern __shared__ float smem1[];
    float* sA[2] = { smem1,                 smem1 + 128 * P1_STR };
    float* sB[2] = { smem1 + 2*128*P1_STR,  smem1 + 3*128*P1_STR };

    const int tid  = threadIdx.x;
    const int m0   = blockIdx.y * 128;
    const int n0   = blockIdx.x * 128;
    const int warp = tid >> 5, lane = tid & 31;
    const int wm   = warp >> 2, wn = warp & 3;     // 2x4 warps, warp tile 64x32
    const int grp  = lane >> 2, tig = lane & 3;

    float acc[4][4][4];
#pragma unroll
    for (int a = 0; a < 4; a++)
#pragma unroll
        for (int b = 0; b < 4; b++)
#pragma unroll
            for (int c = 0; c < 4; c++) acc[a][b][c] = 0.0f;

    p1_issue(sA[0], sB[0], g_xcvt, g_wpcvt, m0, n0, 0, tid);
    asm volatile("cp.async.commit_group;\n");

    for (int s = 0; s < 32; s++) {
        if (s < 31) {
            p1_issue(sA[(s + 1) & 1], sB[(s + 1) & 1], g_xcvt, g_wpcvt,
                     m0, n0, (s + 1) * 32, tid);
            asm volatile("cp.async.commit_group;\n");
            asm volatile("cp.async.wait_group 1;\n");
        } else {
            asm volatile("cp.async.wait_group 0;\n");
        }
        __syncthreads();

        const unsigned* cA = (const unsigned*)sA[s & 1];
        const unsigned* cB = (const unsigned*)sB[s & 1];
#pragma unroll
        for (int kc = 0; kc < 4; kc++) {
            const int kb = kc * 8;
            unsigned afr[4][4], bfr[4][2];
#pragma unroll
            for (int mf = 0; mf < 4; mf++) {
                const unsigned* base = cA + (wm * 64 + mf * 16 + grp) * P1_STR + kb + tig;
                afr[mf][0] = base[0];
                afr[mf][1] = base[8 * P1_STR];
                afr[mf][2] = base[4];
                afr[mf][3] = base[8 * P1_STR + 4];
            }
#pragma unroll
            for (int nf = 0; nf < 4; nf++) {
                const unsigned* base = cB + (wn * 32 + nf * 8 + grp) * P1_STR + kb + tig;
                bfr[nf][0] = base[0];
                bfr[nf][1] = base[4];
            }
#pragma unroll
            for (int mf = 0; mf < 4; mf++)
#pragma unroll
                for (int nf = 0; nf < 4; nf++)
                    mma_tf32(acc[mf][nf], afr[mf], bfr[nf]);
        }
        __syncthreads();
    }

    // epilogue: bias + nonlinearity, scatter time-major
#pragma unroll
    for (int mf = 0; mf < 4; mf++) {
#pragma unroll
        for (int r2 = 0; r2 < 2; r2++) {
            const int m    = m0 + wm * 64 + mf * 16 + grp + r2 * 8;
            const int t    = m & (SLEN - 1);
            const int bidx = m >> 11;
            const size_t ob1024 = ((size_t)t * BATCH + bidx) * (size_t)DIM;
            const size_t ob512  = ((size_t)t * BATCH + bidx) * (size_t)HDIM;
#pragma unroll
            for (int nf = 0; nf < 4; nf++) {
#pragma unroll
                for (int c = 0; c < 2; c++) {
                    const int n = n0 + wn * 32 + nf * 8 + 2 * tig + c;
                    const float v = acc[mf][nf][r2 * 2 + c] + bp[n];
                    if (n < DIM) {
                        g_u[ob1024 + n] = sigmoidf_acc(v);
                    } else if (n < DIM + HDIM) {
                        float sv, cv;
                        sincosf(v, &sv, &cv);
                        g_cosb[ob512 + (n - DIM)] = cv;
                        g_sinb[ob512 + (n - DIM)] = sv;
                    } else if (n < 2 * DIM + HDIM) {
                        g_cand[ob1024 + (n - (DIM + HDIM))] = tanhf(v);
                    } else {
                        g_og[ob1024 + (n - (2 * DIM + HDIM))] = sigmoidf_acc(v);
                    }
                }
            }
        }
    }
}

// =====================================================================
// Phase 2: persistent recurrence, batch-split columns (R10 structure),
// with state-store + publish moved AHEAD of out-write/gate-prefetch.
// CTA c = (jb = c>>2, bcol = c&3): owns j in [32jb,32jb+32), b in
// [4bcol,4bcol+4). 16 flag counters [bcol][qj], 8 producers each.
// =====================================================================
__device__ __forceinline__ void end_barrier() {
    __syncthreads();
    if (threadIdx.x == 0) {
        unsigned gen;
        asm volatile("ld.relaxed.gpu.global.u32 %0, [%1];"
                     : "=r"(gen) : "l"(&g_bar_gen) : "memory");
        unsigned old;
        asm volatile("atom.release.gpu.global.add.u32 %0, [%1], 1;"
                     : "=r"(old) : "l"(&g_bar_count) : "memory");
        if (old == NCTA2 - 1) {
            asm volatile("st.relaxed.gpu.global.u32 [%0], 0;"
                         :: "l"(&g_bar_count) : "memory");
            asm volatile("red.release.gpu.global.add.u32 [%0], 1;"
                         :: "l"(&g_bar_gen) : "memory");
        } else {
            unsigned cur;
            do {
                asm volatile("ld.acquire.gpu.global.u32 %0, [%1];"
                             : "=r"(cur) : "l"(&g_bar_gen) : "memory");
            } while (cur == gen);
        }
    }
    __syncthreads();
}

__global__ void __launch_bounds__(512, 1)
phase2_kernel(const float* __restrict__ Wt,
              const float* __restrict__ bt,
              float* __restrict__ out,
              int write_final) {
    extern __shared__ float smem2[];
    float* s_state = smem2;                   // [4 b][1024 k]
    float* s_red   = smem2 + 4 * DIM;         // [8 jg][2 halves][16]

    const int tid  = threadIdx.x;
    const int lane = tid & 31;
    const int warp = tid >> 5;
    const int ks   = tid & 63;          // k-pair slice
    const int jg   = tid >> 6;          // j group: 8 groups of 4 j
    const int cta  = blockIdx.x;
    const int bcol = cta & 3;
    const int jb   = cta >> 2;
    const int myflag = bcol * 4 + (jb >> 3);

    // persistent Wt registers: w2[jj][i] packs Wt[j][2*(ks+64i)] pair
    ull w2[4][8];
#pragma unroll
    for (int jj = 0; jj < 4; jj++) {
        const int j = 32 * jb + 4 * jg + jj;
#pragma unroll
        for (int i = 0; i < 8; i++)
            w2[jj][i] = *(const ull*)(Wt + (size_t)j * DIM + 2 * (ks + 64 * i));
    }

    // epilogue-thread constants (valid for tid<128): 32 j x 4 b outputs
    const int bl_e  = tid >> 5;
    const int jl_e  = tid & 31;
    const int b_e   = 4 * bcol + bl_e;
    const int jglob = 32 * jb + jl_e;
    const int hp    = jglob >> 1;
    const int jgE   = jl_e >> 2, jjE = jl_e & 3;
    const int iE    = jjE * 4 + bl_e;
    const int iP    = (jjE ^ 1) * 4 + bl_e;

    const int st_bl  = tid >> 6;         // 0..3 for tid<256
    const int st_idx = tid & 63;
    const unsigned s_state_sh = (unsigned)__cvta_generic_to_shared(s_state);

    // gates for step t (prefetched one step ahead)
    float gu = 0.f, gcd = 0.f, gog = 0.f, gc = 0.f, gs = 0.f;
    if (tid < 128) {
        gu  = g_u   [(size_t)b_e * DIM  + jglob];
        gcd = g_cand[(size_t)b_e * DIM  + jglob];
        gog = g_og  [(size_t)b_e * DIM  + jglob];
        gc  = g_cosb[(size_t)b_e * HDIM + hp];
        gs  = g_sinb[(size_t)b_e * HDIM + hp];
    }

    for (int t = 0; t < SLEN; t++) {
        float ps_me = 0.f, ps_pa = 0.f;
        if (t == 0) {
            if (tid < 128) { ps_me = bt[jglob]; ps_pa = bt[jglob ^ 1]; }
        } else {
            const float4* src4 = (const float4*)g_state[t & 1];
            const unsigned tgt = 8u * (unsigned)t;

            // parallel detect: lanes 0-3 of warp 0 spin on my column's quarters
            if (warp == 0 && lane < 4) {
                unsigned cur;
                do {
                    asm volatile("ld.acquire.gpu.global.u32 %0, [%1];"
                                 : "=r"(cur) : "l"(&g_cnt16[bcol * 4 + lane]) : "memory");
                } while (cur < tgt);
            }
            __syncthreads();

            // stage my 4 batches (4KB per quarter, 4 commit groups)
#pragma unroll
            for (int q = 0; q < 4; q++) {
                if (tid < 256) {
                    const int sidx = st_bl * 256 + q * 64 + st_idx;
                    const int gidx = (4 * bcol + st_bl) * 256 + q * 64 + st_idx;
                    asm volatile("cp.async.cg.shared.global [%0], [%1], 16;\n"
                                 :: "r"(s_state_sh + 16u * (unsigned)sidx),
                                    "l"(src4 + gidx));
                }
                asm volatile("cp.async.commit_group;\n");
            }

            // FMA, quarter-pipelined against staging flight
            ull acc[4][4];
#pragma unroll
            for (int jj = 0; jj < 4; jj++)
#pragma unroll
                for (int bl = 0; bl < 4; bl++) acc[jj][bl] = 0ull;

#define P2_FMA_QUARTER(Q)                                                          \
            do {                                                                   \
                __syncthreads();                                                   \
                _Pragma("unroll")                                                  \
                for (int bl = 0; bl < 4; bl++) {                                   \
                    const float* sp = s_state + bl * DIM + 2 * ks + 256 * (Q);     \
                    ull s2a = *(const ull*)(sp);                                   \
                    ull s2b = *(const ull*)(sp + 128);                             \
                    _Pragma("unroll")                                              \
                    for (int jj = 0; jj < 4; jj++) {                               \
                        asm("fma.rn.f32x2 %0, %1, %2, %0;"                         \
                            : "+l"(acc[jj][bl]) : "l"(w2[jj][2 * (Q)]), "l"(s2a)); \
                        asm("fma.rn.f32x2 %0, %1, %2, %0;"                         \
                            : "+l"(acc[jj][bl]) : "l"(w2[jj][2 * (Q) + 1]), "l"(s2b)); \
                    }                                                              \
                }                                                                  \
            } while (0)

            asm volatile("cp.async.wait_group 3;\n");
            P2_FMA_QUARTER(0);
            asm volatile("cp.async.wait_group 2;\n");
            P2_FMA_QUARTER(1);
            asm volatile("cp.async.wait_group 1;\n");
            P2_FMA_QUARTER(2);
            asm volatile("cp.async.wait_group 0;\n");
            P2_FMA_QUARTER(3);

            // collapse pairs, register-halving butterfly over 32 lanes
            float v[16];
#pragma unroll
            for (int jj = 0; jj < 4; jj++)
#pragma unroll
                for (int bl = 0; bl < 4; bl++) {
                    float2 f = *(float2*)&acc[jj][bl];
                    v[jj * 4 + bl] = f.x + f.y;
                }
            {
                const bool lo16 = (lane & 16) == 0;
#pragma unroll
                for (int j = 0; j < 8; j++) {
                    float send = lo16 ? v[j + 8] : v[j];
                    float recv = __shfl_xor_sync(0xffffffffu, send, 16);
                    v[j] = (lo16 ? v[j] : v[j + 8]) + recv;
                }
                const bool lo8 = (lane & 8) == 0;
#pragma unroll
                for (int j = 0; j < 4; j++) {
                    float send = lo8 ? v[j + 4] : v[j];
                    float recv = __shfl_xor_sync(0xffffffffu, send, 8);
                    v[j] = (lo8 ? v[j] : v[j + 4]) + recv;
                }
                const bool lo4 = (lane & 4) == 0;
#pragma unroll
                for (int j = 0; j < 2; j++) {
                    float send = lo4 ? v[j + 2] : v[j];
                    float recv = __shfl_xor_sync(0xffffffffu, send, 4);
                    v[j] = (lo4 ? v[j] : v[j + 2]) + recv;
                }
                const bool lo2 = (lane & 2) == 0;
                {
                    float send = lo2 ? v[1] : v[0];
                    float recv = __shfl_xor_sync(0xffffffffu, send, 2);
                    v[0] = (lo2 ? v[0] : v[1]) + recv;
                }
                v[0] += __shfl_xor_sync(0xffffffffu, v[0], 1);
            }
            if ((lane & 1) == 0)
                s_red[(warp >> 1) * 32 + (warp & 1) * 16 + ((lane >> 1) & 15)] = v[0];
            __syncthreads();

            if (tid < 128) {
                ps_me = s_red[jgE * 32 + iE] + s_red[jgE * 32 + 16 + iE] + bt[jglob];
                ps_pa = s_red[jgE * 32 + iP] + s_red[jgE * 32 + 16 + iP] + bt[jglob ^ 1];
            }
        }

        // rotation + gate; state store FIRST (critical path), publish, then out
        float ns = 0.f;
        if (tid < 128) {
            float ts;
            if (jl_e & 1) ts = ps_pa * gs + ps_me * gc;   // r1 = p0*sin + p1*cos
            else          ts = ps_me * gc - ps_pa * gs;   // r0 = p0*cos - p1*sin
            ns = gu * ts + (1.0f - gu) * gcd;
            __stcg(&g_state[(t + 1) & 1][b_e * DIM + jglob], ns);
        }

        if (t < SLEN - 1) {
            __syncthreads();
            if (tid == 0)
                asm volatile("red.release.gpu.global.add.u32 [%0], 1;"
                             :: "l"(&g_cnt16[myflag]) : "memory");
            if (tid < 128) {
                out[(size_t)b_e * SLEN * DIM + (size_t)t * DIM + jglob] = gog * ns;
                const size_t ob = (size_t)(t + 1) * BATCH + b_e;
                gu  = g_u   [ob * DIM  + jglob];
                gcd = g_cand[ob * DIM  + jglob];
                gog = g_og  [ob * DIM  + jglob];
                gc  = g_cosb[ob * HDIM + hp];
                gs  = g_sinb[ob * HDIM + hp];
            }
        } else {
            if (tid < 128) {
                out[(size_t)b_e * SLEN * DIM + (size_t)t * DIM + jglob] = gog * ns;
                if (write_final)
                    out[(size_t)BATCH * SLEN * DIM + (size_t)b_e * DIM + jglob] = ns;
            }
        }
    }

    // end of run: classic barrier, then CTA0 resets counters
    end_barrier();
    if (cta == 0 && tid == 0) {
#pragma unroll
        for (int q = 0; q < 16; q++)
            asm volatile("st.relaxed.gpu.global.u32 [%0], 0;"
                         :: "l"(&g_cnt16[q]) : "memory");
    }
}

// =====================================================================
extern "C" void kernel_launch(void* const* d_in, const int* in_sizes, int n_in,
                              void* d_out, int out_size) {
    const float* x  = (const float*)d_in[0];
    const float* Wp = (const float*)d_in[1];
    const float* bp = (const float*)d_in[2];
    const float* Wt = (const float*)d_in[3];
    const float* bt = (const float*)d_in[4];
    float* out = (float*)d_out;

    const int smem1 = 4 * 128 * P1_STR * (int)sizeof(float);            // 73728
    const int smem2 = (4 * DIM + 8 * 2 * 16) * (int)sizeof(float);      // 17408
    cudaFuncSetAttribute(phase1_kernel, cudaFuncAttributeMaxDynamicSharedMemorySize, smem1);
    cudaFuncSetAttribute(phase2_kernel, cudaFuncAttributeMaxDynamicSharedMemorySize, smem2);

    const long long need = (long long)BATCH * SLEN * DIM + (long long)BATCH * DIM;
    const int write_final = ((long long)out_size >= need) ? 1 : 0;

    float* xcvt;  cudaGetSymbolAddress((void**)&xcvt,  g_xcvt);
    float* wpcvt; cudaGetSymbolAddress((void**)&wpcvt, g_wpcvt);

    // 1) tf32-round operands once (removes all per-fragment CVTs from mainloop)
    cvt_kernel<<<4096, 256>>>(x,  xcvt,  (BATCH * SLEN * DIM) / 4);
    cvt_kernel<<<1024, 256>>>(Wp, wpcvt, (PDIM * DIM) / 4);
    // 2) projection GEMM + fused gates
    dim3 g1(PDIM / 128, (BATCH * SLEN) / 128);   // (28, 256)
    phase1_kernel<<<g1, 256, smem1>>>(bp);
    // 3) recurrence
    phase2_kernel<<<NCTA2, 512, smem2>>>(Wt, bt, out, write_final);
}